// round 8
// baseline (speedup 1.0000x reference)
#include <cuda_runtime.h>

// PLIF spiking neuron forward:
//   x: [B=32, T=8, C=128, H=32, W=32] f32, tau: [C=128] f32
//   tau_s = sigmoid(tau[c])
//   scan over t: mem = mem*tau_s + x_t; spike = (mem - 1 > 0); mem = (1-spike)*mem
//   out: spikes, same shape as x.
//
// R2 body (proven fastest: 8 front-batched LDG.128 MLP=8, register scan,
// interleaved STG.128, 32 regs) at finer CTA granularity: 128-thread blocks,
// 8192 CTAs, 16 CTAs/SM (same 2048 resident threads) — halves the wave/drain
// scheduling quantum on the 3.46-wave launch. Kernel is at the mixed-R/W HBM
// plateau (~5.83 TB/s, 73% of spec); .CS hints, store batching, grid-stride,
// and persistent layouts all measured slower (R3-R6).

constexpr int B = 32, T = 8, C = 128, H = 32, W = 32;
constexpr int HW   = H * W;          // 1024
constexpr int CHW  = C * HW;         // 131072 (= 2^17)
constexpr int TCHW = T * CHW;        // 1048576
constexpr int N4   = (B * CHW) / 4;  // 1048576 float4-threads

constexpr int THREADS = 128;

__global__ __launch_bounds__(THREADS) void plif_kernel(
    const float4* __restrict__ x4,
    const float*  __restrict__ tau,
    float4*       __restrict__ out4)
{
    int idx = blockIdx.x * THREADS + threadIdx.x;
    if (idx >= N4) return;

    int e   = idx << 2;              // element index within [B, C, H, W] flat
    int b   = e >> 17;               // / CHW
    int rem = e & (CHW - 1);         // within one (C,H,W) slab
    int c   = rem >> 10;             // / HW

    // per-channel leak (broadcast within warp; precise sigmoid)
    float ts = 1.0f / (1.0f + expf(-tau[c]));

    // float4 base index of timestep 0 for this site
    int base = (b * TCHW + rem) >> 2;
    constexpr int tstride = CHW >> 2;  // float4 stride between timesteps

    // Front-batched loads: 8 independent LDG.128 in flight
    float4 v[T];
#pragma unroll
    for (int t = 0; t < T; t++)
        v[t] = x4[base + t * tstride];

    // Register scan; store each spike immediately so v[t] is freed
    float4 mem = make_float4(0.f, 0.f, 0.f, 0.f);
#pragma unroll
    for (int t = 0; t < T; t++) {
        float4 s;
        mem.x = mem.x * ts + v[t].x;
        mem.y = mem.y * ts + v[t].y;
        mem.z = mem.z * ts + v[t].z;
        mem.w = mem.w * ts + v[t].w;
        s.x = (mem.x > 1.0f) ? 1.0f : 0.0f;
        s.y = (mem.y > 1.0f) ? 1.0f : 0.0f;
        s.z = (mem.z > 1.0f) ? 1.0f : 0.0f;
        s.w = (mem.w > 1.0f) ? 1.0f : 0.0f;
        // hard reset: mem = (1-spike)*mem
        if (s.x != 0.0f) mem.x = 0.0f;
        if (s.y != 0.0f) mem.y = 0.0f;
        if (s.z != 0.0f) mem.z = 0.0f;
        if (s.w != 0.0f) mem.w = 0.0f;
        out4[base + t * tstride] = s;
    }
}

extern "C" void kernel_launch(void* const* d_in, const int* in_sizes, int n_in,
                              void* d_out, int out_size)
{
    const float4* x4  = (const float4*)d_in[0];
    const float*  tau = (const float*)d_in[1];
    float4*       o4  = (float4*)d_out;

    int blocks = (N4 + THREADS - 1) / THREADS;   // 8192
    plif_kernel<<<blocks, THREADS>>>(x4, tau, o4);
}

// round 9
// speedup vs baseline: 1.0021x; 1.0021x over previous
#include <cuda_runtime.h>

// PLIF spiking neuron forward — FINAL.
//   x: [B=32, T=8, C=128, H=32, W=32] f32, tau: [C=128] f32
//   tau_s = sigmoid(tau[c])
//   scan over t: mem = mem*tau_s + x_t; spike = (mem - 1 > 0); mem = (1-spike)*mem
//   out: spikes, same shape as x.
//
// Converged configuration (best of 6 measured variants):
//   One thread per (b,c,w-quad) site via float4. 8 front-batched LDG.128
//   (MLP=8), register scan, interleaved STG.128 so each v[t] dies
//   immediately (32 regs, 16 CTAs/SM @ 128 threads, ~83% occupancy).
//   Measured: 36.6µs kernel, 5.83 TB/s (73.7% DRAM busy) — the practical
//   mixed 1:1 R/W HBM3e plateau. Ruled out by experiment: .CS hints (R3/R4),
//   store batching (R3), single-wave grid-stride (R5), persistent + hoisted
//   indexing (R6), 256-thread blocks (R7, tied).

constexpr int B = 32, T = 8, C = 128, H = 32, W = 32;
constexpr int HW   = H * W;          // 1024
constexpr int CHW  = C * HW;         // 131072 (= 2^17)
constexpr int TCHW = T * CHW;        // 1048576
constexpr int N4   = (B * CHW) / 4;  // 1048576 float4-threads

constexpr int THREADS = 128;

__global__ __launch_bounds__(THREADS) void plif_kernel(
    const float4* __restrict__ x4,
    const float*  __restrict__ tau,
    float4*       __restrict__ out4)
{
    int idx = blockIdx.x * THREADS + threadIdx.x;
    if (idx >= N4) return;

    int e   = idx << 2;              // element index within [B, C, H, W] flat
    int b   = e >> 17;               // / CHW
    int rem = e & (CHW - 1);         // within one (C,H,W) slab
    int c   = rem >> 10;             // / HW

    // per-channel leak (broadcast within warp; precise sigmoid)
    float ts = 1.0f / (1.0f + expf(-tau[c]));

    // float4 base index of timestep 0 for this site
    int base = (b * TCHW + rem) >> 2;
    constexpr int tstride = CHW >> 2;  // float4 stride between timesteps

    // Front-batched loads: 8 independent LDG.128 in flight
    float4 v[T];
#pragma unroll
    for (int t = 0; t < T; t++)
        v[t] = x4[base + t * tstride];

    // Register scan; store each spike immediately so v[t] is freed
    float4 mem = make_float4(0.f, 0.f, 0.f, 0.f);
#pragma unroll
    for (int t = 0; t < T; t++) {
        float4 s;
        mem.x = mem.x * ts + v[t].x;
        mem.y = mem.y * ts + v[t].y;
        mem.z = mem.z * ts + v[t].z;
        mem.w = mem.w * ts + v[t].w;
        s.x = (mem.x > 1.0f) ? 1.0f : 0.0f;
        s.y = (mem.y > 1.0f) ? 1.0f : 0.0f;
        s.z = (mem.z > 1.0f) ? 1.0f : 0.0f;
        s.w = (mem.w > 1.0f) ? 1.0f : 0.0f;
        // hard reset: mem = (1-spike)*mem
        if (s.x != 0.0f) mem.x = 0.0f;
        if (s.y != 0.0f) mem.y = 0.0f;
        if (s.z != 0.0f) mem.z = 0.0f;
        if (s.w != 0.0f) mem.w = 0.0f;
        out4[base + t * tstride] = s;
    }
}

extern "C" void kernel_launch(void* const* d_in, const int* in_sizes, int n_in,
                              void* d_out, int out_size)
{
    const float4* x4  = (const float4*)d_in[0];
    const float*  tau = (const float*)d_in[1];
    float4*       o4  = (float4*)d_out;

    int blocks = (N4 + THREADS - 1) / THREADS;   // 8192
    plif_kernel<<<blocks, THREADS>>>(x4, tau, o4);
}

// round 10
// speedup vs baseline: 1.0239x; 1.0218x over previous
#include <cuda_runtime.h>

// PLIF spiking neuron forward — FINAL (converged).
//   x: [B=32, T=8, C=128, H=32, W=32] f32, tau: [C=128] f32
//   tau_s = sigmoid(tau[c])
//   scan over t: mem = mem*tau_s + x_t; spike = (mem - 1 > 0); mem = (1-spike)*mem
//   out: spikes, same shape as x.
//
// Best of 7 measured variants:
//   One thread per (b,c,w-quad) site via float4. 8 front-batched LDG.128
//   (MLP=8), register scan, interleaved STG.128 so each v[t] dies
//   immediately (32 regs, 16 CTAs/SM @ 128 threads, ~83% occupancy).
//   Measured: 36.6-37.6µs kernel, 5.7-5.8 TB/s (72-74% DRAM busy) — the
//   practical mixed 1:1 R/W HBM3e plateau; run-to-run noise ±1µs.
//   Ruled out by experiment: .CS load hints (R3), .CS store hints (R4,
//   clear regression), store batching (R3), single-wave grid-stride (R5),
//   persistent + hoisted indexing (R6), 256-thread blocks (R7, tied).

constexpr int B = 32, T = 8, C = 128, H = 32, W = 32;
constexpr int HW   = H * W;          // 1024
constexpr int CHW  = C * HW;         // 131072 (= 2^17)
constexpr int TCHW = T * CHW;        // 1048576
constexpr int N4   = (B * CHW) / 4;  // 1048576 float4-threads

constexpr int THREADS = 128;

__global__ __launch_bounds__(THREADS) void plif_kernel(
    const float4* __restrict__ x4,
    const float*  __restrict__ tau,
    float4*       __restrict__ out4)
{
    int idx = blockIdx.x * THREADS + threadIdx.x;
    if (idx >= N4) return;

    int e   = idx << 2;              // element index within [B, C, H, W] flat
    int b   = e >> 17;               // / CHW
    int rem = e & (CHW - 1);         // within one (C,H,W) slab
    int c   = rem >> 10;             // / HW

    // per-channel leak (broadcast within warp; precise sigmoid)
    float ts = 1.0f / (1.0f + expf(-tau[c]));

    // float4 base index of timestep 0 for this site
    int base = (b * TCHW + rem) >> 2;
    constexpr int tstride = CHW >> 2;  // float4 stride between timesteps

    // Front-batched loads: 8 independent LDG.128 in flight
    float4 v[T];
#pragma unroll
    for (int t = 0; t < T; t++)
        v[t] = x4[base + t * tstride];

    // Register scan; store each spike immediately so v[t] is freed
    float4 mem = make_float4(0.f, 0.f, 0.f, 0.f);
#pragma unroll
    for (int t = 0; t < T; t++) {
        float4 s;
        mem.x = mem.x * ts + v[t].x;
        mem.y = mem.y * ts + v[t].y;
        mem.z = mem.z * ts + v[t].z;
        mem.w = mem.w * ts + v[t].w;
        s.x = (mem.x > 1.0f) ? 1.0f : 0.0f;
        s.y = (mem.y > 1.0f) ? 1.0f : 0.0f;
        s.z = (mem.z > 1.0f) ? 1.0f : 0.0f;
        s.w = (mem.w > 1.0f) ? 1.0f : 0.0f;
        // hard reset: mem = (1-spike)*mem
        if (s.x != 0.0f) mem.x = 0.0f;
        if (s.y != 0.0f) mem.y = 0.0f;
        if (s.z != 0.0f) mem.z = 0.0f;
        if (s.w != 0.0f) mem.w = 0.0f;
        out4[base + t * tstride] = s;
    }
}

extern "C" void kernel_launch(void* const* d_in, const int* in_sizes, int n_in,
                              void* d_out, int out_size)
{
    const float4* x4  = (const float4*)d_in[0];
    const float*  tau = (const float*)d_in[1];
    float4*       o4  = (float4*)d_out;

    int blocks = (N4 + THREADS - 1) / THREADS;   // 8192
    plif_kernel<<<blocks, THREADS>>>(x4, tau, o4);
}